// round 15
// baseline (speedup 1.0000x reference)
#include <cuda_runtime.h>
#include <cuda_bf16.h>
#include <stdint.h>
#include <math.h>

#define TOK 8192
#define DM 1024
#define SEQ 2048
#define NHEADS 16
#define HDIM 64
#define GK 6144           // 6-term expanded K for projection GEMMs
#define NCH6 96
#define NCH3 48
#define AP_BYTES 144
#define TILE_A 18432      // 128 rows * 144B
#define CHUNK_BYTES (2 * TILE_A)      // A tile + B tile (one 64-wide k chunk)
#define SUP_BYTES (2 * CHUNK_BYTES)   // superchunk: 2 k-chunks = 73728
#define GEMM_SMEM (3 * SUP_BYTES)     // 221184 (occ 1)

// attention tiling
#define AQT 128
#define AKT 64
#define QKP 400
#define VVP 144
#define QS_BYTES (128 * QKP)
#define KS_BYTES (64 * QKP)
#define VS_BYTES (128 * VVP)
#define ATTN_SMEM (QS_BYTES + 2 * KS_BYTES + 2 * VS_BYTES)  // 139264

// epilogue staging pitches (floats)
#define EPI_P 130          // gemm stage: 128x130 fp32 = 66560 B <= GEMM_SMEM
#define AEPI_P 66          // attn stage: 128x66 fp32 = 33792 B <= QS_BYTES

// ---------------- device scratch ----------------
__device__ __align__(1024) __nv_bfloat16 g_A2[(size_t)TOK * GK];
__device__ __align__(1024) __nv_bfloat16 g_B2[4][(size_t)DM * GK];
__device__ __align__(1024) __nv_bfloat16 g_Q6[(size_t)64 * SEQ * 192];
__device__ __align__(1024) __nv_bfloat16 g_K6[(size_t)64 * SEQ * 192];
__device__ __align__(1024) __nv_bfloat16 g_VT[(size_t)64 * 128 * SEQ];

// ---------------- PTX helpers ----------------
__device__ __forceinline__ uint32_t smem_u32(const void* p) {
    uint32_t a;
    asm("{ .reg .u64 t; cvta.to.shared.u64 t, %1; cvt.u32.u64 %0, t; }" : "=r"(a) : "l"(p));
    return a;
}
#define CP_ASYNC16(dst, src) \
    asm volatile("cp.async.cg.shared.global [%0], [%1], 16;" :: "r"((uint32_t)(dst)), "l"(src) : "memory")
#define CP_COMMIT() asm volatile("cp.async.commit_group;" ::: "memory")
#define CP_WAIT(n)  asm volatile("cp.async.wait_group %0;" :: "n"(n) : "memory")
#define LDSM_X4(r, addr) \
    asm volatile("ldmatrix.sync.aligned.m8n8.x4.shared.b16 {%0,%1,%2,%3}, [%4];" \
        : "=r"((r)[0]), "=r"((r)[1]), "=r"((r)[2]), "=r"((r)[3]) : "r"(addr))
#define MMA16816(d, a, b) \
    asm volatile("mma.sync.aligned.m16n8k16.row.col.f32.bf16.bf16.f32 " \
        "{%0,%1,%2,%3}, {%4,%5,%6,%7}, {%8,%9}, {%0,%1,%2,%3};" \
        : "+f"((d)[0]), "+f"((d)[1]), "+f"((d)[2]), "+f"((d)[3]) \
        : "r"((a)[0]), "r"((a)[1]), "r"((a)[2]), "r"((a)[3]), "r"((b)[0]), "r"((b)[1]))

__device__ __forceinline__ uint32_t pack_bf16x2(float lo, float hi) {
    uint32_t r;
    asm("cvt.rn.bf16x2.f32 %0, %1, %2;" : "=r"(r) : "f"(hi), "f"(lo));
    return r;
}
__device__ __forceinline__ uint32_t residual_bf16x2(float lo, float hi, uint32_t packed) {
    __nv_bfloat162 p = *(__nv_bfloat162*)&packed;
    return pack_bf16x2(lo - __bfloat162float(p.x), hi - __bfloat162float(p.y));
}

// 3-way split [h, m, l] (attention q6/k6 contract)
__device__ __forceinline__ void store_split_hml(__nv_bfloat16* base, int region_stride,
                                                float v0, float v1) {
    uint32_t hp = pack_bf16x2(v0, v1);
    *(uint32_t*)(base) = hp;
    __nv_bfloat162 h2 = *(__nv_bfloat162*)&hp;
    float r0 = v0 - __bfloat162float(h2.x);
    float r1 = v1 - __bfloat162float(h2.y);
    uint32_t mp = pack_bf16x2(r0, r1);
    *(uint32_t*)(base + region_stride) = mp;
    __nv_bfloat162 m2 = *(__nv_bfloat162*)&mp;
    uint32_t lp = pack_bf16x2(r0 - __bfloat162float(m2.x), r1 - __bfloat162float(m2.y));
    *(uint32_t*)(base + 2 * region_stride) = lp;
}

// 3-term A-split [h, m, h] (fc GEMM contract: pairs with B=[H,H,M])
__device__ __forceinline__ void store_split_hmh(__nv_bfloat16* base, int region_stride,
                                                float v0, float v1) {
    uint32_t hp = pack_bf16x2(v0, v1);
    *(uint32_t*)(base) = hp;
    *(uint32_t*)(base + 2 * region_stride) = hp;
    __nv_bfloat162 h2 = *(__nv_bfloat162*)&hp;
    uint32_t mp = pack_bf16x2(v0 - __bfloat162float(h2.x), v1 - __bfloat162float(h2.y));
    *(uint32_t*)(base + region_stride) = mp;
}

// ---------------------------------------------------------------------------
// convert_A: fp32 [M,1024] -> A2 [M, 6144]  regions [h,m,h | m,l,h]
// ---------------------------------------------------------------------------
__global__ __launch_bounds__(256) void convert_A(const float* __restrict__ X,
                                                 __nv_bfloat16* __restrict__ A2)
{
    size_t idx = (size_t)blockIdx.x * 256 + threadIdx.x;
    int k = (int)(idx & 1023);
    size_t m = idx >> 10;
    float v = X[idx];
    __nv_bfloat16 h = __float2bfloat16(v);
    float r1 = v - __bfloat162float(h);
    __nv_bfloat16 mm = __float2bfloat16(r1);
    __nv_bfloat16 ll = __float2bfloat16(r1 - __bfloat162float(mm));
    __nv_bfloat16* row = A2 + m * GK + k;
    row[0] = h; row[1024] = mm; row[2048] = h;
    row[3072] = mm; row[4096] = ll; row[5120] = h;
}

// convert_B4: fused 4-weight conversion. z selects W and output panel.
__global__ __launch_bounds__(256) void convert_B4(
    const float* __restrict__ W0, const float* __restrict__ W1,
    const float* __restrict__ W2, const float* __restrict__ W3,
    __nv_bfloat16* __restrict__ B2)
{
    __shared__ float s[64][129];
    const int z = blockIdx.z;
    const float* W = (z == 0) ? W0 : (z == 1) ? W1 : (z == 2) ? W2 : W3;
    __nv_bfloat16* Bz = B2 + (size_t)z * DM * GK;
    const int k0 = blockIdx.x * 64;
    const int n0 = blockIdx.y * 128;
    const int tid = threadIdx.x;
    for (int i = tid; i < 64 * 128; i += 256) {
        int kk = i >> 7, nn = i & 127;
        s[kk][nn] = W[(size_t)(k0 + kk) * DM + n0 + nn];
    }
    __syncthreads();
    for (int i = tid; i < 128 * 64; i += 256) {
        int r = i >> 6, c = i & 63;
        float v = s[c][r];
        __nv_bfloat16 h = __float2bfloat16(v);
        float r1 = v - __bfloat162float(h);
        __nv_bfloat16 mm = __float2bfloat16(r1);
        __nv_bfloat16 ll = __float2bfloat16(r1 - __bfloat162float(mm));
        __nv_bfloat16* row = Bz + (size_t)(n0 + r) * GK + k0 + c;
        row[0] = h; row[1024] = h; row[2048] = mm;
        row[3072] = mm; row[4096] = h; row[5120] = ll;
    }
}

// ---------------------------------------------------------------------------
// Shared GEMM mainloop: 256 thr, 8 warps, warp tile 64x32.
// Superchunk pipeline: 128 k-elems (2 chunks) per CP_WAIT+sync, 3 stages.
// Chunk order inside a superchunk preserved -> bit-identical accumulation.
// ---------------------------------------------------------------------------
struct GemmCtx {
    uint32_t sb;
    int wm, wn, lane;
    int a_row_off, a_kh, b_n_off, b_kh;
};

__device__ __forceinline__ void gemm_mainloop(
    const __nv_bfloat16* __restrict__ A, const __nv_bfloat16* __restrict__ B,
    int bm, int bn, int nch, const GemmCtx& g, float acc[4][4][4])
{
    const int tid = threadIdx.x;
    const int ld_row = tid >> 3;
    const int ld_c16 = tid & 7;
    const __nv_bfloat16* gA0 = A + (size_t)bm * GK;
    const __nv_bfloat16* gB0 = B + (size_t)bn * GK;

    // load one superchunk (2 k-chunks: A0,B0,A1,B1) into stage st
    auto load_sup = [&](int st, int sup) {
        uint32_t base = g.sb + st * SUP_BYTES;
#pragma unroll
        for (int half = 0; half < 2; half++) {
            const __nv_bfloat16* gA = gA0 + (sup * 2 + half) * 64;
            const __nv_bfloat16* gB = gB0 + (sup * 2 + half) * 64;
            uint32_t dA = base + half * CHUNK_BYTES;
            uint32_t dB = dA + TILE_A;
#pragma unroll
            for (int i = 0; i < 4; i++) {
                int row = ld_row + i * 32;
                CP_ASYNC16(dA + row * AP_BYTES + ld_c16 * 16, gA + (size_t)row * GK + ld_c16 * 8);
                CP_ASYNC16(dB + row * AP_BYTES + ld_c16 * 16, gB + (size_t)row * GK + ld_c16 * 8);
            }
        }
    };

    const int nsup = nch >> 1;
    load_sup(0, 0);
    CP_COMMIT();
    load_sup(1, 1);
    CP_COMMIT();

    int stg = 0;
    for (int sup = 0; sup < nsup; sup++) {
        if (sup + 1 < nsup) { CP_WAIT(1); } else { CP_WAIT(0); }
        __syncthreads();
        if (sup + 2 < nsup) {
            int nstg = stg + 2; if (nstg >= 3) nstg -= 3;
            load_sup(nstg, sup + 2);
            CP_COMMIT();
        }
#pragma unroll
        for (int half = 0; half < 2; half++) {
            const uint32_t sA = g.sb + stg * SUP_BYTES + half * CHUNK_BYTES;
            const uint32_t sB = sA + TILE_A;
#pragma unroll
            for (int ks = 0; ks < 4; ks++) {
                uint32_t a[4][4];
#pragma unroll
                for (int mi = 0; mi < 4; mi++) {
                    uint32_t row = (uint32_t)(g.wm * 64 + mi * 16 + g.a_row_off);
                    LDSM_X4(a[mi], sA + row * AP_BYTES + ks * 32 + g.a_kh * 16);
                }
                uint32_t b[4][2];
#pragma unroll
                for (int j2 = 0; j2 < 2; j2++) {
                    uint32_t row = (uint32_t)(g.wn * 32 + j2 * 16 + g.b_n_off);
                    uint32_t t[4];
                    LDSM_X4(t, sB + row * AP_BYTES + ks * 32 + g.b_kh * 16);
                    b[2 * j2][0] = t[0]; b[2 * j2][1] = t[1];
                    b[2 * j2 + 1][0] = t[2]; b[2 * j2 + 1][1] = t[3];
                }
#pragma unroll
                for (int mi = 0; mi < 4; mi++)
#pragma unroll
                    for (int nj = 0; nj < 4; nj++)
                        MMA16816(acc[mi][nj], a[mi], b[nj]);
            }
        }
        if (++stg == 3) stg = 0;
    }
}

__device__ __forceinline__ GemmCtx make_ctx(uint32_t sb) {
    const int tid = threadIdx.x;
    GemmCtx g;
    g.sb = sb;
    const int wid = tid >> 5;
    g.lane = tid & 31;
    g.wm = wid >> 2; g.wn = wid & 3;
    const int lr = g.lane & 7, sel = g.lane >> 3;
    g.a_row_off = ((sel & 1) << 3) + lr;
    g.a_kh = sel >> 1;
    g.b_n_off = ((sel >> 1) << 3) + lr;
    g.b_kh = sel & 1;
    return g;
}

// ---------------------------------------------------------------------------
// gemm_qkv: fused Q/K/V projection. blockIdx.z: 0=Q->q6, 1=K->k6, 2=V->VT.
// ---------------------------------------------------------------------------
__global__ __launch_bounds__(256, 1)
void gemm_qkv(const __nv_bfloat16* __restrict__ A, const __nv_bfloat16* __restrict__ B2all,
              __nv_bfloat16* __restrict__ q6, __nv_bfloat16* __restrict__ k6,
              __nv_bfloat16* __restrict__ VT, float qscale)
{
    extern __shared__ __align__(128) char smemf[];
    GemmCtx g = make_ctx(smem_u32(smemf));
    const int z = blockIdx.z;
    const int bm = blockIdx.y * 128;
    const int bn = blockIdx.x * 128;
    const __nv_bfloat16* B = B2all + (size_t)z * DM * GK;
    const int nch = (z == 2) ? NCH3 : NCH6;

    float acc[4][4][4];
#pragma unroll
    for (int i = 0; i < 4; i++)
#pragma unroll
        for (int j = 0; j < 4; j++)
#pragma unroll
            for (int e = 0; e < 4; e++) acc[i][j][e] = 0.f;

    gemm_mainloop(A, B, bm, bn, nch, g, acc);

    // stage fp32 tile in smem (mainloop smem dead after final superchunk)
    __syncthreads();
    float* stg = (float*)smemf;
    const int col = (g.lane & 3) * 2;
    const int rbase = g.lane >> 2;
#pragma unroll
    for (int mi = 0; mi < 4; mi++) {
#pragma unroll
        for (int nj = 0; nj < 4; nj++) {
            int row = g.wm * 64 + mi * 16 + rbase;
            int c0 = g.wn * 32 + nj * 8 + col;
            stg[row * EPI_P + c0]     = acc[mi][nj][0];
            stg[row * EPI_P + c0 + 1] = acc[mi][nj][1];
            stg[(row + 8) * EPI_P + c0]     = acc[mi][nj][2];
            stg[(row + 8) * EPI_P + c0 + 1] = acc[mi][nj][3];
        }
    }
    __syncthreads();

    const int wid = threadIdx.x >> 5;
    const int lane = g.lane;

    if (z == 2) {
        // V: write split transposed layout VT[bh][Vh d | Vl d][s] directly.
        const int b = bm >> 11;
        const int s0 = bm & 2047;
        for (int task = wid; task < 128; task += 8) {
            int h2 = task >> 6, d = task & 63;
            int bh = b * 16 + (bn >> 6) + h2;
            __nv_bfloat16* baseH = VT + ((size_t)bh * 128 + d) * SEQ + s0;
            __nv_bfloat16* baseL = baseH + (size_t)64 * SEQ;
#pragma unroll
            for (int j = 0; j < 4; j++) {
                int ss = lane + j * 32;
                float v = stg[ss * EPI_P + h2 * 64 + d];
                __nv_bfloat16 hh = __float2bfloat16(v);
                baseH[ss] = hh;
                baseL[ss] = __float2bfloat16(v - __bfloat162float(hh));
            }
        }
        return;
    }

    // Q/K: [h,m,l] split epilogue -> q6 / k6
    __nv_bfloat16* Y = (z == 0) ? q6 : k6;
    const float scale = (z == 0) ? qscale : 1.0f;
    for (int task = wid; task < 256; task += 8) {
        int tok = task >> 1;
        int h2 = task & 1;
        int row = bm + tok;
        int b = row >> 11, s = row & 2047;
        int head = (bn >> 6) + h2;
        float v0 = stg[tok * EPI_P + h2 * 64 + lane * 2]     * scale;
        float v1 = stg[tok * EPI_P + h2 * 64 + lane * 2 + 1] * scale;
        __nv_bfloat16* base = Y + ((size_t)(b * 16 + head) * SEQ + s) * 192 + lane * 2;
        store_split_hml(base, 64, v0, v1);
    }
}

// gemm_mma: plain fp32 output (fc_out)
__global__ __launch_bounds__(256, 1)
void gemm_mma(const __nv_bfloat16* __restrict__ A, const __nv_bfloat16* __restrict__ B,
              float* __restrict__ C, int nch)
{
    extern __shared__ __align__(128) char smem2[];
    GemmCtx g = make_ctx(smem_u32(smem2));
    const int bm = blockIdx.y * 128;
    const int bn = blockIdx.x * 128;

    float acc[4][4][4];
#pragma unroll
    for (int i = 0; i < 4; i++)
#pragma unroll
        for (int j = 0; j < 4; j++)
#pragma unroll
            for (int e = 0; e < 4; e++) acc[i][j][e] = 0.f;

    gemm_mainloop(A, B, bm, bn, nch, g, acc);

    const int col = (g.lane & 3) * 2;
    const int rbase = g.lane >> 2;
#pragma unroll
    for (int mi = 0; mi < 4; mi++) {
#pragma unroll
        for (int nj = 0; nj < 4; nj++) {
            int row = bm + g.wm * 64 + mi * 16 + rbase;
            int c0 = bn + g.wn * 32 + nj * 8 + col;
            *(float2*)&C[(size_t)row * DM + c0] =
                make_float2(acc[mi][nj][0], acc[mi][nj][1]);
            *(float2*)&C[(size_t)(row + 8) * DM + c0] =
                make_float2(acc[mi][nj][2], acc[mi][nj][3]);
        }
    }
}

// ---------------------------------------------------------------------------
// attn_tc (unchanged, proven): tensor-core flash attention; staged coalesced
// [h,m,h] epilogue into A2 regions 0..2.
// ---------------------------------------------------------------------------
__global__ __launch_bounds__(256, 1)
void attn_tc(const __nv_bfloat16* __restrict__ Q6, const __nv_bfloat16* __restrict__ K6,
             const __nv_bfloat16* __restrict__ VT, __nv_bfloat16* __restrict__ A2)
{
    extern __shared__ __align__(128) char asm_[];
    const uint32_t sb = smem_u32(asm_);
    const uint32_t Qs = sb;
    const uint32_t Ks0 = sb + QS_BYTES;
    const uint32_t Vs0 = Ks0 + 2 * KS_BYTES;

    const int tid = threadIdx.x;
    const int w = tid >> 5, lane = tid & 31;
    const int bh = blockIdx.y;
    const int q0 = blockIdx.x * AQT;

    const int lr = lane & 7, sel = lane >> 3;
    const int a_row_off = ((sel & 1) << 3) + lr;
    const int a_kh = sel >> 1;
    const int b_n_off = ((sel >> 1) << 3) + lr;
    const int b_kh = sel & 1;

    const char* gQ = (const char*)(Q6 + ((size_t)bh * SEQ + q0) * 192);
    const char* gK = (const char*)(K6 + (size_t)bh * SEQ * 192);
    const char* gV = (const char*)(VT + (size_t)bh * 128 * SEQ);

    auto load_kv = [&](int st, int t) {
        const int k0 = t * AKT;
        uint32_t dK = Ks0 + st * KS_BYTES;
#pragma unroll
        for (int i = 0; i < 6; i++) {
            int idx = tid + i * 256;
            int row = idx / 24, c = idx % 24;
            CP_ASYNC16(dK + row * QKP + c * 16, gK + (size_t)(k0 + row) * 384 + c * 16);
        }
        uint32_t dV = Vs0 + st * VS_BYTES;
#pragma unroll
        for (int i = 0; i < 4; i++) {
            int idx = tid + i * 256;
            int row = idx >> 3, c = idx & 7;
            CP_ASYNC16(dV + row * VVP + c * 16, gV + ((size_t)row * SEQ + k0) * 2 + c * 16);
        }
    };

#pragma unroll
    for (int i = 0; i < 12; i++) {
        int idx = tid + i * 256;
        int row = idx / 24, c = idx % 24;
        CP_ASYNC16(Qs + row * QKP + c * 16, gQ + (size_t)row * 384 + c * 16);
    }
    load_kv(0, 0);
    CP_COMMIT();
    load_kv(1, 1);
    CP_COMMIT();

    uint32_t qa[3][4][4];
    float d[8][4];
#pragma unroll
    for (int i = 0; i < 8; i++)
#pragma unroll
        for (int e = 0; e < 4; e++) d[i][e] = 0.f;
    float m_lo = -1e30f, m_hi = -1e30f, l_lo = 0.f, l_hi = 0.f;

    const int NIT = SEQ / AKT;
    for (int it = 0; it < NIT; it++) {
        if (it + 1 < NIT) { CP_WAIT(1); } else { CP_WAIT(0); }
        __syncthreads();

        if (it == 0) {
#pragma unroll
            for (int r = 0; r < 3; r++)
#pragma unroll
                for (int t4 = 0; t4 < 4; t4++)
                    LDSM_X4(qa[r][t4],
                            Qs + (w * 16 + a_row_off) * QKP + r * 128 + t4 * 32 + a_kh * 16);
        }

        const int st = it & 1;
        const uint32_t Ks = Ks0 + st * KS_BYTES;
        const uint32_t Vs = Vs0 + st * VS_BYTES;

        float c[8][4];
#pragma unroll
        for (int i = 0; i < 8; i++)
#pragma unroll
            for (int e = 0; e < 4; e++) c[i][e] = 0.f;

#pragma unroll
        for (int kb = 0; kb < 4; kb++) {
            const uint32_t krow = Ks + (kb * 16 + b_n_off) * QKP + b_kh * 16;
#pragma unroll
            for (int t4 = 0; t4 < 4; t4++) {
                uint32_t bb[4];
                LDSM_X4(bb, krow + 0 * 128 + t4 * 32);
                MMA16816(c[kb * 2],     qa[0][t4], bb);
                MMA16816(c[kb * 2 + 1], qa[0][t4], bb + 2);
                MMA16816(c[kb * 2],     qa[1][t4], bb);
                MMA16816(c[kb * 2 + 1], qa[1][t4], bb + 2);
                MMA16816(c[kb * 2],     qa[2][t4], bb);
                MMA16816(c[kb * 2 + 1], qa[2][t4], bb + 2);
                LDSM_X4(bb, krow + 1 * 128 + t4 * 32);
                MMA16816(c[kb * 2],     qa[0][t4], bb);
                MMA16816(c[kb * 2 + 1], qa[0][t4], bb + 2);
                MMA16816(c[kb * 2],     qa[1][t4], bb);
                MMA16816(c[kb * 2 + 1], qa[1][t4], bb + 2);
                LDSM_X4(bb, krow + 2 * 128 + t4 * 32);
                MMA16816(c[kb * 2],     qa[0][t4], bb);
                MMA16816(c[kb * 2 + 1], qa[0][t4], bb + 2);
            }
        }

        float tmx_lo = -1e30f, tmx_hi = -1e30f;
#pragma unroll
        for (int t = 0; t < 8; t++) {
            tmx_lo = fmaxf(tmx_lo, fmaxf(c[t][0], c[t][1]));
            tmx_hi = fmaxf(tmx_hi, fmaxf(c[t][2], c[t][3]));
        }
        tmx_lo = fmaxf(tmx_lo, __shfl_xor_sync(0xffffffffu, tmx_lo, 1));
        tmx_lo = fmaxf(tmx_lo, __shfl_xor_sync(0xffffffffu, tmx_lo, 2));
        tmx_hi = fmaxf(tmx_hi, __shfl_xor_sync(0xffffffffu, tmx_hi, 1));
        tmx_hi = fmaxf(tmx_hi, __shfl_xor_sync(0xffffffffu, tmx_hi, 2));

        float mn_lo = fmaxf(m_lo, tmx_lo);
        float mn_hi = fmaxf(m_hi, tmx_hi);
        float corr_lo = exp2f(m_lo - mn_lo);
        float corr_hi = exp2f(m_hi - mn_hi);

        float ps_lo = 0.f, ps_hi = 0.f;
#pragma unroll
        for (int t = 0; t < 8; t++) {
            c[t][0] = exp2f(c[t][0] - mn_lo);
            c[t][1] = exp2f(c[t][1] - mn_lo);
            c[t][2] = exp2f(c[t][2] - mn_hi);
            c[t][3] = exp2f(c[t][3] - mn_hi);
            ps_lo += c[t][0] + c[t][1];
            ps_hi += c[t][2] + c[t][3];
        }
        ps_lo += __shfl_xor_sync(0xffffffffu, ps_lo, 1);
        ps_lo += __shfl_xor_sync(0xffffffffu, ps_lo, 2);
        ps_hi += __shfl_xor_sync(0xffffffffu, ps_hi, 1);
        ps_hi += __shfl_xor_sync(0xffffffffu, ps_hi, 2);
        l_lo = l_lo * corr_lo + ps_lo;
        l_hi = l_hi * corr_hi + ps_hi;
        m_lo = mn_lo; m_hi = mn_hi;
#pragma unroll
        for (int nb = 0; nb < 8; nb++) {
            d[nb][0] *= corr_lo; d[nb][1] *= corr_lo;
            d[nb][2] *= corr_hi; d[nb][3] *= corr_hi;
        }

        uint32_t aph[4][4], apl[4][4];
#pragma unroll
        for (int kt = 0; kt < 4; kt++) {
            int t0 = 2 * kt, t1 = t0 + 1;
            aph[kt][0] = pack_bf16x2(c[t0][0], c[t0][1]);
            aph[kt][1] = pack_bf16x2(c[t0][2], c[t0][3]);
            aph[kt][2] = pack_bf16x2(c[t1][0], c[t1][1]);
            aph[kt][3] = pack_bf16x2(c[t1][2], c[t1][3]);
            apl[kt][0] = residual_bf16x2(c[t0][0], c[t0][1], aph[kt][0]);
            apl[kt][1] = residual_bf16x2(c[t0][2], c[t0][3], aph[kt][1]);
            apl[kt][2] = residual_bf16x2(c[t1][0], c[t1][1], aph[kt][2]);
            apl[kt][3] = residual_bf16x2(c[t1][2], c[t1][3], aph[kt][3]);
        }

#pragma unroll
        for (int nbp = 0; nbp < 4; nbp++) {
            const uint32_t vrow = Vs + (nbp * 16 + b_n_off) * VVP + b_kh * 16;
#pragma unroll
            for (int kt = 0; kt < 4; kt++) {
                uint32_t tH[4], tL[4];
                LDSM_X4(tH, vrow + kt * 32);
                LDSM_X4(tL, vrow + 64 * VVP + kt * 32);
                MMA16816(d[nbp * 2],     aph[kt], tH);
                MMA16816(d[nbp * 2 + 1], aph[kt], tH + 2);
                MMA16816(d[nbp * 2],     apl[kt], tH);
                MMA16816(d[nbp * 2 + 1], apl[kt], tH + 2);
                MMA16816(d[nbp * 2],     aph[kt], tL);
                MMA16816(d[nbp * 2 + 1], aph[kt], tL + 2);
            }
        }

        __syncthreads();
        if (it + 2 < NIT) {
            load_kv(it & 1, it + 2);
            CP_COMMIT();
        }
    }

    // ---- staged coalesced epilogue: [h,m,h] A-split into A2 regions 0..2 ----
    float inv_lo = 1.f / l_lo, inv_hi = 1.f / l_hi;
    float* stg = (float*)asm_;
    const int row0 = w * 16 + (lane >> 2);
    const int colb = (lane & 3) * 2;
#pragma unroll
    for (int nb = 0; nb < 8; nb++) {
        stg[row0 * AEPI_P + colb + nb * 8]     = d[nb][0] * inv_lo;
        stg[row0 * AEPI_P + colb + nb * 8 + 1] = d[nb][1] * inv_lo;
        stg[(row0 + 8) * AEPI_P + colb + nb * 8]     = d[nb][2] * inv_hi;
        stg[(row0 + 8) * AEPI_P + colb + nb * 8 + 1] = d[nb][3] * inv_hi;
    }
    __syncthreads();

    const int h = bh & 15;
    const int btok = (bh >> 4) * SEQ;
    for (int task = w; task < 128; task += 8) {
        int row = btok + q0 + task;
        float v0 = stg[task * AEPI_P + lane * 2];
        float v1 = stg[task * AEPI_P + lane * 2 + 1];
        __nv_bfloat16* base = A2 + (size_t)row * GK + h * 64 + lane * 2;
        store_split_hmh(base, 1024, v0, v1);
    }
}

// ---------------------------------------------------------------------------
extern "C" void kernel_launch(void* const* d_in, const int* in_sizes, int n_in,
                              void* d_out, int out_size)
{
    const float* x  = (const float*)d_in[0];
    const float* Wq = (const float*)d_in[1];
    const float* Wk = (const float*)d_in[2];
    const float* Wv = (const float*)d_in[3];
    const float* Wo = (const float*)d_in[4];
    float* out = (float*)d_out;

    __nv_bfloat16 *a2, *b2, *q6, *k6, *vt;
    cudaGetSymbolAddress((void**)&a2, g_A2);
    cudaGetSymbolAddress((void**)&b2, g_B2);
    cudaGetSymbolAddress((void**)&q6, g_Q6);
    cudaGetSymbolAddress((void**)&k6, g_K6);
    cudaGetSymbolAddress((void**)&vt, g_VT);
    __nv_bfloat16* b2o = b2 + 3 * (size_t)DM * GK;

    cudaFuncSetAttribute(gemm_qkv, cudaFuncAttributeMaxDynamicSharedMemorySize, GEMM_SMEM);
    cudaFuncSetAttribute(gemm_mma, cudaFuncAttributeMaxDynamicSharedMemorySize, GEMM_SMEM);
    cudaFuncSetAttribute(attn_tc, cudaFuncAttributeMaxDynamicSharedMemorySize, ATTN_SMEM);

    const int convA_blocks = (int)(((size_t)TOK * DM) / 256);
    const float qscale = 0.125f * 1.4426950408889634f;

    convert_A<<<convA_blocks, 256>>>(x, a2);                               // 1
    dim3 convB_grid(16, 8, 4);
    convert_B4<<<convB_grid, 256>>>(Wq, Wk, Wv, Wo, b2);                   // 2

    dim3 qkv_grid(DM / 128, TOK / 128, 3);                                 // 1536 CTAs
    gemm_qkv<<<qkv_grid, 256, GEMM_SMEM>>>(a2, b2, q6, k6, vt, qscale);    // 3

    dim3 agrid(SEQ / AQT, 64);
    attn_tc<<<agrid, 256, ATTN_SMEM>>>(q6, k6, vt, a2);                    // 4 -> A2 [h,m,h]

    dim3 ggrid(DM / 128, TOK / 128);
    gemm_mma<<<ggrid, 256, GEMM_SMEM>>>(a2, b2o, out, NCH3);               // 5 fc_out
}

// round 16
// speedup vs baseline: 1.0964x; 1.0964x over previous
#include <cuda_runtime.h>
#include <cuda_bf16.h>
#include <stdint.h>
#include <math.h>

#define TOK 8192
#define DM 1024
#define SEQ 2048
#define NHEADS 16
#define HDIM 64
#define GK 6144           // 6-term expanded K for projection GEMMs
#define NCH6 96
#define NCH3 48
#define AP_BYTES 144
#define TILE_A 18432      // 128 rows * 144B
#define STG_BYTES (2 * TILE_A)   // A tile + B tile per stage
#define GEMM_SMEM (3 * STG_BYTES) // 110592 (occ 2)

// attention tiling (3-stage K/V pipeline)
#define AQT 128
#define AKT 64
#define QKP 400
#define VVP 144
#define QS_BYTES (128 * QKP)
#define KS_BYTES (64 * QKP)
#define VS_BYTES (128 * VVP)
#define ATTN_SMEM (QS_BYTES + 3 * KS_BYTES + 3 * VS_BYTES)  // 183296

// epilogue staging pitches (floats)
#define EPI_P 130          // gemm stage: 128x130 fp32 = 66560 B <= GEMM_SMEM
#define AEPI_P 66          // attn stage: 128x66 fp32 = 33792 B <= QS_BYTES

// ---------------- device scratch ----------------
__device__ __align__(1024) __nv_bfloat16 g_A2[(size_t)TOK * GK];
__device__ __align__(1024) __nv_bfloat16 g_B2[4][(size_t)DM * GK];
__device__ __align__(1024) __nv_bfloat16 g_Q6[(size_t)64 * SEQ * 192];
__device__ __align__(1024) __nv_bfloat16 g_K6[(size_t)64 * SEQ * 192];
__device__ __align__(1024) __nv_bfloat16 g_VT[(size_t)64 * 128 * SEQ];

// ---------------- PTX helpers ----------------
__device__ __forceinline__ uint32_t smem_u32(const void* p) {
    uint32_t a;
    asm("{ .reg .u64 t; cvta.to.shared.u64 t, %1; cvt.u32.u64 %0, t; }" : "=r"(a) : "l"(p));
    return a;
}
#define CP_ASYNC16(dst, src) \
    asm volatile("cp.async.cg.shared.global [%0], [%1], 16;" :: "r"((uint32_t)(dst)), "l"(src) : "memory")
#define CP_COMMIT() asm volatile("cp.async.commit_group;" ::: "memory")
#define CP_WAIT(n)  asm volatile("cp.async.wait_group %0;" :: "n"(n) : "memory")
#define LDSM_X4(r, addr) \
    asm volatile("ldmatrix.sync.aligned.m8n8.x4.shared.b16 {%0,%1,%2,%3}, [%4];" \
        : "=r"((r)[0]), "=r"((r)[1]), "=r"((r)[2]), "=r"((r)[3]) : "r"(addr))
#define MMA16816(d, a, b) \
    asm volatile("mma.sync.aligned.m16n8k16.row.col.f32.bf16.bf16.f32 " \
        "{%0,%1,%2,%3}, {%4,%5,%6,%7}, {%8,%9}, {%0,%1,%2,%3};" \
        : "+f"((d)[0]), "+f"((d)[1]), "+f"((d)[2]), "+f"((d)[3]) \
        : "r"((a)[0]), "r"((a)[1]), "r"((a)[2]), "r"((a)[3]), "r"((b)[0]), "r"((b)[1]))

__device__ __forceinline__ uint32_t pack_bf16x2(float lo, float hi) {
    uint32_t r;
    asm("cvt.rn.bf16x2.f32 %0, %1, %2;" : "=r"(r) : "f"(hi), "f"(lo));
    return r;
}
__device__ __forceinline__ uint32_t residual_bf16x2(float lo, float hi, uint32_t packed) {
    __nv_bfloat162 p = *(__nv_bfloat162*)&packed;
    return pack_bf16x2(lo - __bfloat162float(p.x), hi - __bfloat162float(p.y));
}

// 3-way split [h, m, l] (attention q6/k6 contract)
__device__ __forceinline__ void store_split_hml(__nv_bfloat16* base, int region_stride,
                                                float v0, float v1) {
    uint32_t hp = pack_bf16x2(v0, v1);
    *(uint32_t*)(base) = hp;
    __nv_bfloat162 h2 = *(__nv_bfloat162*)&hp;
    float r0 = v0 - __bfloat162float(h2.x);
    float r1 = v1 - __bfloat162float(h2.y);
    uint32_t mp = pack_bf16x2(r0, r1);
    *(uint32_t*)(base + region_stride) = mp;
    __nv_bfloat162 m2 = *(__nv_bfloat162*)&mp;
    uint32_t lp = pack_bf16x2(r0 - __bfloat162float(m2.x), r1 - __bfloat162float(m2.y));
    *(uint32_t*)(base + 2 * region_stride) = lp;
}

// 3-term A-split [h, m, h] (fc GEMM contract: pairs with B=[H,H,M])
__device__ __forceinline__ void store_split_hmh(__nv_bfloat16* base, int region_stride,
                                                float v0, float v1) {
    uint32_t hp = pack_bf16x2(v0, v1);
    *(uint32_t*)(base) = hp;
    *(uint32_t*)(base + 2 * region_stride) = hp;
    __nv_bfloat162 h2 = *(__nv_bfloat162*)&hp;
    uint32_t mp = pack_bf16x2(v0 - __bfloat162float(h2.x), v1 - __bfloat162float(h2.y));
    *(uint32_t*)(base + region_stride) = mp;
}

// ---------------------------------------------------------------------------
// convert_A: fp32 [M,1024] -> A2 [M, 6144]  regions [h,m,h | m,l,h]
// ---------------------------------------------------------------------------
__global__ __launch_bounds__(256) void convert_A(const float* __restrict__ X,
                                                 __nv_bfloat16* __restrict__ A2)
{
    size_t idx = (size_t)blockIdx.x * 256 + threadIdx.x;
    int k = (int)(idx & 1023);
    size_t m = idx >> 10;
    float v = X[idx];
    __nv_bfloat16 h = __float2bfloat16(v);
    float r1 = v - __bfloat162float(h);
    __nv_bfloat16 mm = __float2bfloat16(r1);
    __nv_bfloat16 ll = __float2bfloat16(r1 - __bfloat162float(mm));
    __nv_bfloat16* row = A2 + m * GK + k;
    row[0] = h; row[1024] = mm; row[2048] = h;
    row[3072] = mm; row[4096] = ll; row[5120] = h;
}

// convert_B4: fused 4-weight conversion. z selects W and output panel.
__global__ __launch_bounds__(256) void convert_B4(
    const float* __restrict__ W0, const float* __restrict__ W1,
    const float* __restrict__ W2, const float* __restrict__ W3,
    __nv_bfloat16* __restrict__ B2)
{
    __shared__ float s[64][129];
    const int z = blockIdx.z;
    const float* W = (z == 0) ? W0 : (z == 1) ? W1 : (z == 2) ? W2 : W3;
    __nv_bfloat16* Bz = B2 + (size_t)z * DM * GK;
    const int k0 = blockIdx.x * 64;
    const int n0 = blockIdx.y * 128;
    const int tid = threadIdx.x;
    for (int i = tid; i < 64 * 128; i += 256) {
        int kk = i >> 7, nn = i & 127;
        s[kk][nn] = W[(size_t)(k0 + kk) * DM + n0 + nn];
    }
    __syncthreads();
    for (int i = tid; i < 128 * 64; i += 256) {
        int r = i >> 6, c = i & 63;
        float v = s[c][r];
        __nv_bfloat16 h = __float2bfloat16(v);
        float r1 = v - __bfloat162float(h);
        __nv_bfloat16 mm = __float2bfloat16(r1);
        __nv_bfloat16 ll = __float2bfloat16(r1 - __bfloat162float(mm));
        __nv_bfloat16* row = Bz + (size_t)(n0 + r) * GK + k0 + c;
        row[0] = h; row[1024] = h; row[2048] = mm;
        row[3072] = mm; row[4096] = h; row[5120] = ll;
    }
}

// ---------------------------------------------------------------------------
// Shared GEMM mainloop (R14 proven: 256 thr, 8 warps, warp tile 64x32,
// 3-stage cp.async pipeline, single sync per chunk, occ 2)
// ---------------------------------------------------------------------------
struct GemmCtx {
    uint32_t sb;
    int wm, wn, lane;
    int a_row_off, a_kh, b_n_off, b_kh;
};

__device__ __forceinline__ void gemm_mainloop(
    const __nv_bfloat16* __restrict__ A, const __nv_bfloat16* __restrict__ B,
    int bm, int bn, int nch, const GemmCtx& g, float acc[4][4][4])
{
    const int tid = threadIdx.x;
    const int ld_row = tid >> 3;
    const int ld_c16 = tid & 7;
    const __nv_bfloat16* gA0 = A + (size_t)bm * GK;
    const __nv_bfloat16* gB0 = B + (size_t)bn * GK;

    auto load_tile = [&](int st, int kt) {
        const __nv_bfloat16* gA = gA0 + kt * 64;
        const __nv_bfloat16* gB = gB0 + kt * 64;
        uint32_t dA = g.sb + st * STG_BYTES;
        uint32_t dB = dA + TILE_A;
#pragma unroll
        for (int i = 0; i < 4; i++) {
            int row = ld_row + i * 32;
            CP_ASYNC16(dA + row * AP_BYTES + ld_c16 * 16, gA + (size_t)row * GK + ld_c16 * 8);
            CP_ASYNC16(dB + row * AP_BYTES + ld_c16 * 16, gB + (size_t)row * GK + ld_c16 * 8);
        }
    };

    load_tile(0, 0);
    CP_COMMIT();
    load_tile(1, 1);
    CP_COMMIT();

    int stg = 0;
    for (int kt = 0; kt < nch; kt++) {
        if (kt + 1 < nch) { CP_WAIT(1); } else { CP_WAIT(0); }
        __syncthreads();
        if (kt + 2 < nch) {
            int nstg = stg + 2; if (nstg >= 3) nstg -= 3;
            load_tile(nstg, kt + 2);
            CP_COMMIT();
        }
        const uint32_t sA = g.sb + stg * STG_BYTES;
        const uint32_t sB = sA + TILE_A;
#pragma unroll
        for (int ks = 0; ks < 4; ks++) {
            uint32_t a[4][4];
#pragma unroll
            for (int mi = 0; mi < 4; mi++) {
                uint32_t row = (uint32_t)(g.wm * 64 + mi * 16 + g.a_row_off);
                LDSM_X4(a[mi], sA + row * AP_BYTES + ks * 32 + g.a_kh * 16);
            }
            uint32_t b[4][2];
#pragma unroll
            for (int j2 = 0; j2 < 2; j2++) {
                uint32_t row = (uint32_t)(g.wn * 32 + j2 * 16 + g.b_n_off);
                uint32_t t[4];
                LDSM_X4(t, sB + row * AP_BYTES + ks * 32 + g.b_kh * 16);
                b[2 * j2][0] = t[0]; b[2 * j2][1] = t[1];
                b[2 * j2 + 1][0] = t[2]; b[2 * j2 + 1][1] = t[3];
            }
#pragma unroll
            for (int mi = 0; mi < 4; mi++)
#pragma unroll
                for (int nj = 0; nj < 4; nj++)
                    MMA16816(acc[mi][nj], a[mi], b[nj]);
        }
        if (++stg == 3) stg = 0;
    }
}

__device__ __forceinline__ GemmCtx make_ctx(uint32_t sb) {
    const int tid = threadIdx.x;
    GemmCtx g;
    g.sb = sb;
    const int wid = tid >> 5;
    g.lane = tid & 31;
    g.wm = wid >> 2; g.wn = wid & 3;
    const int lr = g.lane & 7, sel = g.lane >> 3;
    g.a_row_off = ((sel & 1) << 3) + lr;
    g.a_kh = sel >> 1;
    g.b_n_off = ((sel >> 1) << 3) + lr;
    g.b_kh = sel & 1;
    return g;
}

// ---------------------------------------------------------------------------
// gemm_qkv: fused Q/K/V projection. blockIdx.z: 0=Q->q6, 1=K->k6, 2=V->VT.
// ---------------------------------------------------------------------------
__global__ __launch_bounds__(256, 2)
void gemm_qkv(const __nv_bfloat16* __restrict__ A, const __nv_bfloat16* __restrict__ B2all,
              __nv_bfloat16* __restrict__ q6, __nv_bfloat16* __restrict__ k6,
              __nv_bfloat16* __restrict__ VT, float qscale)
{
    extern __shared__ __align__(128) char smemf[];
    GemmCtx g = make_ctx(smem_u32(smemf));
    const int z = blockIdx.z;
    const int bm = blockIdx.y * 128;
    const int bn = blockIdx.x * 128;
    const __nv_bfloat16* B = B2all + (size_t)z * DM * GK;
    const int nch = (z == 2) ? NCH3 : NCH6;

    float acc[4][4][4];
#pragma unroll
    for (int i = 0; i < 4; i++)
#pragma unroll
        for (int j = 0; j < 4; j++)
#pragma unroll
            for (int e = 0; e < 4; e++) acc[i][j][e] = 0.f;

    gemm_mainloop(A, B, bm, bn, nch, g, acc);

    // stage fp32 tile in smem (mainloop smem dead after final chunk)
    __syncthreads();
    float* stg = (float*)smemf;
    const int col = (g.lane & 3) * 2;
    const int rbase = g.lane >> 2;
#pragma unroll
    for (int mi = 0; mi < 4; mi++) {
#pragma unroll
        for (int nj = 0; nj < 4; nj++) {
            int row = g.wm * 64 + mi * 16 + rbase;
            int c0 = g.wn * 32 + nj * 8 + col;
            stg[row * EPI_P + c0]     = acc[mi][nj][0];
            stg[row * EPI_P + c0 + 1] = acc[mi][nj][1];
            stg[(row + 8) * EPI_P + c0]     = acc[mi][nj][2];
            stg[(row + 8) * EPI_P + c0 + 1] = acc[mi][nj][3];
        }
    }
    __syncthreads();

    const int wid = threadIdx.x >> 5;
    const int lane = g.lane;

    if (z == 2) {
        // V: write split transposed layout VT[bh][Vh d | Vl d][s] directly.
        const int b = bm >> 11;
        const int s0 = bm & 2047;
        for (int task = wid; task < 128; task += 8) {
            int h2 = task >> 6, d = task & 63;
            int bh = b * 16 + (bn >> 6) + h2;
            __nv_bfloat16* baseH = VT + ((size_t)bh * 128 + d) * SEQ + s0;
            __nv_bfloat16* baseL = baseH + (size_t)64 * SEQ;
#pragma unroll
            for (int j = 0; j < 4; j++) {
                int ss = lane + j * 32;
                float v = stg[ss * EPI_P + h2 * 64 + d];
                __nv_bfloat16 hh = __float2bfloat16(v);
                baseH[ss] = hh;
                baseL[ss] = __float2bfloat16(v - __bfloat162float(hh));
            }
        }
        return;
    }

    // Q/K: [h,m,l] split epilogue -> q6 / k6
    __nv_bfloat16* Y = (z == 0) ? q6 : k6;
    const float scale = (z == 0) ? qscale : 1.0f;
    for (int task = wid; task < 256; task += 8) {
        int tok = task >> 1;
        int h2 = task & 1;
        int row = bm + tok;
        int b = row >> 11, s = row & 2047;
        int head = (bn >> 6) + h2;
        float v0 = stg[tok * EPI_P + h2 * 64 + lane * 2]     * scale;
        float v1 = stg[tok * EPI_P + h2 * 64 + lane * 2 + 1] * scale;
        __nv_bfloat16* base = Y + ((size_t)(b * 16 + head) * SEQ + s) * 192 + lane * 2;
        store_split_hml(base, 64, v0, v1);
    }
}

// gemm_mma: plain fp32 output (fc_out)
__global__ __launch_bounds__(256, 2)
void gemm_mma(const __nv_bfloat16* __restrict__ A, const __nv_bfloat16* __restrict__ B,
              float* __restrict__ C, int nch)
{
    extern __shared__ __align__(128) char smem2[];
    GemmCtx g = make_ctx(smem_u32(smem2));
    const int bm = blockIdx.y * 128;
    const int bn = blockIdx.x * 128;

    float acc[4][4][4];
#pragma unroll
    for (int i = 0; i < 4; i++)
#pragma unroll
        for (int j = 0; j < 4; j++)
#pragma unroll
            for (int e = 0; e < 4; e++) acc[i][j][e] = 0.f;

    gemm_mainloop(A, B, bm, bn, nch, g, acc);

    const int col = (g.lane & 3) * 2;
    const int rbase = g.lane >> 2;
#pragma unroll
    for (int mi = 0; mi < 4; mi++) {
#pragma unroll
        for (int nj = 0; nj < 4; nj++) {
            int row = bm + g.wm * 64 + mi * 16 + rbase;
            int c0 = bn + g.wn * 32 + nj * 8 + col;
            *(float2*)&C[(size_t)row * DM + c0] =
                make_float2(acc[mi][nj][0], acc[mi][nj][1]);
            *(float2*)&C[(size_t)(row + 8) * DM + c0] =
                make_float2(acc[mi][nj][2], acc[mi][nj][3]);
        }
    }
}

// ---------------------------------------------------------------------------
// attn_tc: tensor-core flash attention, 3-stage K/V pipeline (single sync
// per iteration); staged coalesced [h,m,h] epilogue into A2 regions 0..2.
// ---------------------------------------------------------------------------
__global__ __launch_bounds__(256, 1)
void attn_tc(const __nv_bfloat16* __restrict__ Q6, const __nv_bfloat16* __restrict__ K6,
             const __nv_bfloat16* __restrict__ VT, __nv_bfloat16* __restrict__ A2)
{
    extern __shared__ __align__(128) char asm_[];
    const uint32_t sb = smem_u32(asm_);
    const uint32_t Qs = sb;
    const uint32_t Ks0 = sb + QS_BYTES;
    const uint32_t Vs0 = Ks0 + 3 * KS_BYTES;

    const int tid = threadIdx.x;
    const int w = tid >> 5, lane = tid & 31;
    const int bh = blockIdx.y;
    const int q0 = blockIdx.x * AQT;

    const int lr = lane & 7, sel = lane >> 3;
    const int a_row_off = ((sel & 1) << 3) + lr;
    const int a_kh = sel >> 1;
    const int b_n_off = ((sel >> 1) << 3) + lr;
    const int b_kh = sel & 1;

    const char* gQ = (const char*)(Q6 + ((size_t)bh * SEQ + q0) * 192);
    const char* gK = (const char*)(K6 + (size_t)bh * SEQ * 192);
    const char* gV = (const char*)(VT + (size_t)bh * 128 * SEQ);

    auto load_kv = [&](int st, int t) {
        const int k0 = t * AKT;
        uint32_t dK = Ks0 + st * KS_BYTES;
#pragma unroll
        for (int i = 0; i < 6; i++) {
            int idx = tid + i * 256;
            int row = idx / 24, c = idx % 24;
            CP_ASYNC16(dK + row * QKP + c * 16, gK + (size_t)(k0 + row) * 384 + c * 16);
        }
        uint32_t dV = Vs0 + st * VS_BYTES;
#pragma unroll
        for (int i = 0; i < 4; i++) {
            int idx = tid + i * 256;
            int row = idx >> 3, c = idx & 7;
            CP_ASYNC16(dV + row * VVP + c * 16, gV + ((size_t)row * SEQ + k0) * 2 + c * 16);
        }
    };

#pragma unroll
    for (int i = 0; i < 12; i++) {
        int idx = tid + i * 256;
        int row = idx / 24, c = idx % 24;
        CP_ASYNC16(Qs + row * QKP + c * 16, gQ + (size_t)row * 384 + c * 16);
    }
    load_kv(0, 0);
    CP_COMMIT();
    load_kv(1, 1);
    CP_COMMIT();

    uint32_t qa[3][4][4];
    float d[8][4];
#pragma unroll
    for (int i = 0; i < 8; i++)
#pragma unroll
        for (int e = 0; e < 4; e++) d[i][e] = 0.f;
    float m_lo = -1e30f, m_hi = -1e30f, l_lo = 0.f, l_hi = 0.f;

    const int NIT = SEQ / AKT;
    int stg3 = 0;
    for (int it = 0; it < NIT; it++) {
        if (it + 1 < NIT) { CP_WAIT(1); } else { CP_WAIT(0); }
        __syncthreads();
        if (it + 2 < NIT) {
            int nstg = stg3 + 2; if (nstg >= 3) nstg -= 3;
            load_kv(nstg, it + 2);
            CP_COMMIT();
        }

        if (it == 0) {
#pragma unroll
            for (int r = 0; r < 3; r++)
#pragma unroll
                for (int t4 = 0; t4 < 4; t4++)
                    LDSM_X4(qa[r][t4],
                            Qs + (w * 16 + a_row_off) * QKP + r * 128 + t4 * 32 + a_kh * 16);
        }

        const uint32_t Ks = Ks0 + stg3 * KS_BYTES;
        const uint32_t Vs = Vs0 + stg3 * VS_BYTES;

        float c[8][4];
#pragma unroll
        for (int i = 0; i < 8; i++)
#pragma unroll
            for (int e = 0; e < 4; e++) c[i][e] = 0.f;

#pragma unroll
        for (int kb = 0; kb < 4; kb++) {
            const uint32_t krow = Ks + (kb * 16 + b_n_off) * QKP + b_kh * 16;
#pragma unroll
            for (int t4 = 0; t4 < 4; t4++) {
                uint32_t bb[4];
                LDSM_X4(bb, krow + 0 * 128 + t4 * 32);
                MMA16816(c[kb * 2],     qa[0][t4], bb);
                MMA16816(c[kb * 2 + 1], qa[0][t4], bb + 2);
                MMA16816(c[kb * 2],     qa[1][t4], bb);
                MMA16816(c[kb * 2 + 1], qa[1][t4], bb + 2);
                MMA16816(c[kb * 2],     qa[2][t4], bb);
                MMA16816(c[kb * 2 + 1], qa[2][t4], bb + 2);
                LDSM_X4(bb, krow + 1 * 128 + t4 * 32);
                MMA16816(c[kb * 2],     qa[0][t4], bb);
                MMA16816(c[kb * 2 + 1], qa[0][t4], bb + 2);
                MMA16816(c[kb * 2],     qa[1][t4], bb);
                MMA16816(c[kb * 2 + 1], qa[1][t4], bb + 2);
                LDSM_X4(bb, krow + 2 * 128 + t4 * 32);
                MMA16816(c[kb * 2],     qa[0][t4], bb);
                MMA16816(c[kb * 2 + 1], qa[0][t4], bb + 2);
            }
        }

        float tmx_lo = -1e30f, tmx_hi = -1e30f;
#pragma unroll
        for (int t = 0; t < 8; t++) {
            tmx_lo = fmaxf(tmx_lo, fmaxf(c[t][0], c[t][1]));
            tmx_hi = fmaxf(tmx_hi, fmaxf(c[t][2], c[t][3]));
        }
        tmx_lo = fmaxf(tmx_lo, __shfl_xor_sync(0xffffffffu, tmx_lo, 1));
        tmx_lo = fmaxf(tmx_lo, __shfl_xor_sync(0xffffffffu, tmx_lo, 2));
        tmx_hi = fmaxf(tmx_hi, __shfl_xor_sync(0xffffffffu, tmx_hi, 1));
        tmx_hi = fmaxf(tmx_hi, __shfl_xor_sync(0xffffffffu, tmx_hi, 2));

        float mn_lo = fmaxf(m_lo, tmx_lo);
        float mn_hi = fmaxf(m_hi, tmx_hi);
        float corr_lo = exp2f(m_lo - mn_lo);
        float corr_hi = exp2f(m_hi - mn_hi);

        float ps_lo = 0.f, ps_hi = 0.f;
#pragma unroll
        for (int t = 0; t < 8; t++) {
            c[t][0] = exp2f(c[t][0] - mn_lo);
            c[t][1] = exp2f(c[t][1] - mn_lo);
            c[t][2] = exp2f(c[t][2] - mn_hi);
            c[t][3] = exp2f(c[t][3] - mn_hi);
            ps_lo += c[t][0] + c[t][1];
            ps_hi += c[t][2] + c[t][3];
        }
        ps_lo += __shfl_xor_sync(0xffffffffu, ps_lo, 1);
        ps_lo += __shfl_xor_sync(0xffffffffu, ps_lo, 2);
        ps_hi += __shfl_xor_sync(0xffffffffu, ps_hi, 1);
        ps_hi += __shfl_xor_sync(0xffffffffu, ps_hi, 2);
        l_lo = l_lo * corr_lo + ps_lo;
        l_hi = l_hi * corr_hi + ps_hi;
        m_lo = mn_lo; m_hi = mn_hi;
#pragma unroll
        for (int nb = 0; nb < 8; nb++) {
            d[nb][0] *= corr_lo; d[nb][1] *= corr_lo;
            d[nb][2] *= corr_hi; d[nb][3] *= corr_hi;
        }

        uint32_t aph[4][4], apl[4][4];
#pragma unroll
        for (int kt = 0; kt < 4; kt++) {
            int t0 = 2 * kt, t1 = t0 + 1;
            aph[kt][0] = pack_bf16x2(c[t0][0], c[t0][1]);
            aph[kt][1] = pack_bf16x2(c[t0][2], c[t0][3]);
            aph[kt][2] = pack_bf16x2(c[t1][0], c[t1][1]);
            aph[kt][3] = pack_bf16x2(c[t1][2], c[t1][3]);
            apl[kt][0] = residual_bf16x2(c[t0][0], c[t0][1], aph[kt][0]);
            apl[kt][1] = residual_bf16x2(c[t0][2], c[t0][3], aph[kt][1]);
            apl[kt][2] = residual_bf16x2(c[t1][0], c[t1][1], aph[kt][2]);
            apl[kt][3] = residual_bf16x2(c[t1][2], c[t1][3], aph[kt][3]);
        }

#pragma unroll
        for (int nbp = 0; nbp < 4; nbp++) {
            const uint32_t vrow = Vs + (nbp * 16 + b_n_off) * VVP + b_kh * 16;
#pragma unroll
            for (int kt = 0; kt < 4; kt++) {
                uint32_t tH[4], tL[4];
                LDSM_X4(tH, vrow + kt * 32);
                LDSM_X4(tL, vrow + 64 * VVP + kt * 32);
                MMA16816(d[nbp * 2],     aph[kt], tH);
                MMA16816(d[nbp * 2 + 1], aph[kt], tH + 2);
                MMA16816(d[nbp * 2],     apl[kt], tH);
                MMA16816(d[nbp * 2 + 1], apl[kt], tH + 2);
                MMA16816(d[nbp * 2],     aph[kt], tL);
                MMA16816(d[nbp * 2 + 1], aph[kt], tL + 2);
            }
        }

        if (++stg3 == 3) stg3 = 0;
    }

    // ---- staged coalesced epilogue: [h,m,h] A-split into A2 regions 0..2 ----
    __syncthreads();   // all warps done with smem stages
    float inv_lo = 1.f / l_lo, inv_hi = 1.f / l_hi;
    float* stg = (float*)asm_;
    const int row0 = w * 16 + (lane >> 2);
    const int colb = (lane & 3) * 2;
#pragma unroll
    for (int nb = 0; nb < 8; nb++) {
        stg[row0 * AEPI_P + colb + nb * 8]     = d[nb][0] * inv_lo;
        stg[row0 * AEPI_P + colb + nb * 8 + 1] = d[nb][1] * inv_lo;
        stg[(row0 + 8) * AEPI_P + colb + nb * 8]     = d[nb][2] * inv_hi;
        stg[(row0 + 8) * AEPI_P + colb + nb * 8 + 1] = d[nb][3] * inv_hi;
    }
    __syncthreads();

    const int h = bh & 15;
    const int btok = (bh >> 4) * SEQ;
    for (int task = w; task < 128; task += 8) {
        int row = btok + q0 + task;
        float v0 = stg[task * AEPI_P + lane * 2];
        float v1 = stg[task * AEPI_P + lane * 2 + 1];
        __nv_bfloat16* base = A2 + (size_t)row * GK + h * 64 + lane * 2;
        store_split_hmh(base, 1024, v0, v1);
    }
}

// ---------------------------------------------------------------------------
extern "C" void kernel_launch(void* const* d_in, const int* in_sizes, int n_in,
                              void* d_out, int out_size)
{
    const float* x  = (const float*)d_in[0];
    const float* Wq = (const float*)d_in[1];
    const float* Wk = (const float*)d_in[2];
    const float* Wv = (const float*)d_in[3];
    const float* Wo = (const float*)d_in[4];
    float* out = (float*)d_out;

    __nv_bfloat16 *a2, *b2, *q6, *k6, *vt;
    cudaGetSymbolAddress((void**)&a2, g_A2);
    cudaGetSymbolAddress((void**)&b2, g_B2);
    cudaGetSymbolAddress((void**)&q6, g_Q6);
    cudaGetSymbolAddress((void**)&k6, g_K6);
    cudaGetSymbolAddress((void**)&vt, g_VT);
    __nv_bfloat16* b2o = b2 + 3 * (size_t)DM * GK;

    cudaFuncSetAttribute(gemm_qkv, cudaFuncAttributeMaxDynamicSharedMemorySize, GEMM_SMEM);
    cudaFuncSetAttribute(gemm_mma, cudaFuncAttributeMaxDynamicSharedMemorySize, GEMM_SMEM);
    cudaFuncSetAttribute(attn_tc, cudaFuncAttributeMaxDynamicSharedMemorySize, ATTN_SMEM);

    const int convA_blocks = (int)(((size_t)TOK * DM) / 256);
    const float qscale = 0.125f * 1.4426950408889634f;

    convert_A<<<convA_blocks, 256>>>(x, a2);                               // 1
    dim3 convB_grid(16, 8, 4);
    convert_B4<<<convB_grid, 256>>>(Wq, Wk, Wv, Wo, b2);                   // 2

    dim3 qkv_grid(DM / 128, TOK / 128, 3);                                 // 1536 CTAs
    gemm_qkv<<<qkv_grid, 256, GEMM_SMEM>>>(a2, b2, q6, k6, vt, qscale);    // 3

    dim3 agrid(SEQ / AQT, 64);
    attn_tc<<<agrid, 256, ATTN_SMEM>>>(q6, k6, vt, a2);                    // 4 -> A2 [h,m,h]

    dim3 ggrid(DM / 128, TOK / 128);
    gemm_mma<<<ggrid, 256, GEMM_SMEM>>>(a2, b2o, out, NCH3);               // 5 fc_out
}

// round 17
// speedup vs baseline: 1.1019x; 1.0050x over previous
#include <cuda_runtime.h>
#include <cuda_bf16.h>
#include <stdint.h>
#include <math.h>

#define TOK 8192
#define DM 1024
#define SEQ 2048
#define NHEADS 16
#define HDIM 64
#define GK 6144           // 6-term expanded K for projection GEMMs
#define NCH6 96
#define NCH3 48
#define AP_BYTES 144
#define TILE_A 18432      // 128 rows * 144B
#define STG_BYTES (2 * TILE_A)   // A tile + B tile per stage
#define GEMM_SMEM (3 * STG_BYTES) // 110592 (occ 2)

// attention tiling: 128-key tiles, 2-stage K/V pipeline
#define AQT 128
#define AKT 128
#define QKP 400
#define VVP 272           // 128 keys * 2B + 16 pad
#define QS_BYTES (128 * QKP)          // 51200
#define KS_BYTES (128 * QKP)          // 51200
#define VS_BYTES (128 * VVP)          // 34816
#define ATTN_SMEM (QS_BYTES + 2 * KS_BYTES + 2 * VS_BYTES)  // 223232

// epilogue staging pitches (floats)
#define EPI_P 130          // gemm stage: 128x130 fp32 = 66560 B <= GEMM_SMEM
#define AEPI_P 66          // attn stage: 128x66 fp32 = 33792 B <= QS_BYTES

// ---------------- device scratch ----------------
__device__ __align__(1024) __nv_bfloat16 g_A2[(size_t)TOK * GK];
__device__ __align__(1024) __nv_bfloat16 g_B2[4][(size_t)DM * GK];
__device__ __align__(1024) __nv_bfloat16 g_Q6[(size_t)64 * SEQ * 192];
__device__ __align__(1024) __nv_bfloat16 g_K6[(size_t)64 * SEQ * 192];
__device__ __align__(1024) __nv_bfloat16 g_VT[(size_t)64 * 128 * SEQ];

// ---------------- PTX helpers ----------------
__device__ __forceinline__ uint32_t smem_u32(const void* p) {
    uint32_t a;
    asm("{ .reg .u64 t; cvta.to.shared.u64 t, %1; cvt.u32.u64 %0, t; }" : "=r"(a) : "l"(p));
    return a;
}
#define CP_ASYNC16(dst, src) \
    asm volatile("cp.async.cg.shared.global [%0], [%1], 16;" :: "r"((uint32_t)(dst)), "l"(src) : "memory")
#define CP_COMMIT() asm volatile("cp.async.commit_group;" ::: "memory")
#define CP_WAIT(n)  asm volatile("cp.async.wait_group %0;" :: "n"(n) : "memory")
#define LDSM_X4(r, addr) \
    asm volatile("ldmatrix.sync.aligned.m8n8.x4.shared.b16 {%0,%1,%2,%3}, [%4];" \
        : "=r"((r)[0]), "=r"((r)[1]), "=r"((r)[2]), "=r"((r)[3]) : "r"(addr))
#define MMA16816(d, a, b) \
    asm volatile("mma.sync.aligned.m16n8k16.row.col.f32.bf16.bf16.f32 " \
        "{%0,%1,%2,%3}, {%4,%5,%6,%7}, {%8,%9}, {%0,%1,%2,%3};" \
        : "+f"((d)[0]), "+f"((d)[1]), "+f"((d)[2]), "+f"((d)[3]) \
        : "r"((a)[0]), "r"((a)[1]), "r"((a)[2]), "r"((a)[3]), "r"((b)[0]), "r"((b)[1]))

__device__ __forceinline__ uint32_t pack_bf16x2(float lo, float hi) {
    uint32_t r;
    asm("cvt.rn.bf16x2.f32 %0, %1, %2;" : "=r"(r) : "f"(hi), "f"(lo));
    return r;
}
__device__ __forceinline__ uint32_t residual_bf16x2(float lo, float hi, uint32_t packed) {
    __nv_bfloat162 p = *(__nv_bfloat162*)&packed;
    return pack_bf16x2(lo - __bfloat162float(p.x), hi - __bfloat162float(p.y));
}

// 3-way split [h, m, l] (attention q6/k6 contract)
__device__ __forceinline__ void store_split_hml(__nv_bfloat16* base, int region_stride,
                                                float v0, float v1) {
    uint32_t hp = pack_bf16x2(v0, v1);
    *(uint32_t*)(base) = hp;
    __nv_bfloat162 h2 = *(__nv_bfloat162*)&hp;
    float r0 = v0 - __bfloat162float(h2.x);
    float r1 = v1 - __bfloat162float(h2.y);
    uint32_t mp = pack_bf16x2(r0, r1);
    *(uint32_t*)(base + region_stride) = mp;
    __nv_bfloat162 m2 = *(__nv_bfloat162*)&mp;
    uint32_t lp = pack_bf16x2(r0 - __bfloat162float(m2.x), r1 - __bfloat162float(m2.y));
    *(uint32_t*)(base + 2 * region_stride) = lp;
}

// 3-term A-split [h, m, h] (fc GEMM contract: pairs with B=[H,H,M])
__device__ __forceinline__ void store_split_hmh(__nv_bfloat16* base, int region_stride,
                                                float v0, float v1) {
    uint32_t hp = pack_bf16x2(v0, v1);
    *(uint32_t*)(base) = hp;
    *(uint32_t*)(base + 2 * region_stride) = hp;
    __nv_bfloat162 h2 = *(__nv_bfloat162*)&hp;
    uint32_t mp = pack_bf16x2(v0 - __bfloat162float(h2.x), v1 - __bfloat162float(h2.y));
    *(uint32_t*)(base + region_stride) = mp;
}

// ---------------------------------------------------------------------------
// convert_A: fp32 [M,1024] -> A2 [M, 6144]  regions [h,m,h | m,l,h]
// ---------------------------------------------------------------------------
__global__ __launch_bounds__(256) void convert_A(const float* __restrict__ X,
                                                 __nv_bfloat16* __restrict__ A2)
{
    size_t idx = (size_t)blockIdx.x * 256 + threadIdx.x;
    int k = (int)(idx & 1023);
    size_t m = idx >> 10;
    float v = X[idx];
    __nv_bfloat16 h = __float2bfloat16(v);
    float r1 = v - __bfloat162float(h);
    __nv_bfloat16 mm = __float2bfloat16(r1);
    __nv_bfloat16 ll = __float2bfloat16(r1 - __bfloat162float(mm));
    __nv_bfloat16* row = A2 + m * GK + k;
    row[0] = h; row[1024] = mm; row[2048] = h;
    row[3072] = mm; row[4096] = ll; row[5120] = h;
}

// convert_B4: fused 4-weight conversion. z selects W and output panel.
__global__ __launch_bounds__(256) void convert_B4(
    const float* __restrict__ W0, const float* __restrict__ W1,
    const float* __restrict__ W2, const float* __restrict__ W3,
    __nv_bfloat16* __restrict__ B2)
{
    __shared__ float s[64][129];
    const int z = blockIdx.z;
    const float* W = (z == 0) ? W0 : (z == 1) ? W1 : (z == 2) ? W2 : W3;
    __nv_bfloat16* Bz = B2 + (size_t)z * DM * GK;
    const int k0 = blockIdx.x * 64;
    const int n0 = blockIdx.y * 128;
    const int tid = threadIdx.x;
    for (int i = tid; i < 64 * 128; i += 256) {
        int kk = i >> 7, nn = i & 127;
        s[kk][nn] = W[(size_t)(k0 + kk) * DM + n0 + nn];
    }
    __syncthreads();
    for (int i = tid; i < 128 * 64; i += 256) {
        int r = i >> 6, c = i & 63;
        float v = s[c][r];
        __nv_bfloat16 h = __float2bfloat16(v);
        float r1 = v - __bfloat162float(h);
        __nv_bfloat16 mm = __float2bfloat16(r1);
        __nv_bfloat16 ll = __float2bfloat16(r1 - __bfloat162float(mm));
        __nv_bfloat16* row = Bz + (size_t)(n0 + r) * GK + k0 + c;
        row[0] = h; row[1024] = h; row[2048] = mm;
        row[3072] = mm; row[4096] = h; row[5120] = ll;
    }
}

// ---------------------------------------------------------------------------
// Shared GEMM mainloop (R14 proven: 256 thr, 8 warps, warp tile 64x32,
// 3-stage cp.async pipeline, single sync per chunk, occ 2)
// ---------------------------------------------------------------------------
struct GemmCtx {
    uint32_t sb;
    int wm, wn, lane;
    int a_row_off, a_kh, b_n_off, b_kh;
};

__device__ __forceinline__ void gemm_mainloop(
    const __nv_bfloat16* __restrict__ A, const __nv_bfloat16* __restrict__ B,
    int bm, int bn, int nch, const GemmCtx& g, float acc[4][4][4])
{
    const int tid = threadIdx.x;
    const int ld_row = tid >> 3;
    const int ld_c16 = tid & 7;
    const __nv_bfloat16* gA0 = A + (size_t)bm * GK;
    const __nv_bfloat16* gB0 = B + (size_t)bn * GK;

    auto load_tile = [&](int st, int kt) {
        const __nv_bfloat16* gA = gA0 + kt * 64;
        const __nv_bfloat16* gB = gB0 + kt * 64;
        uint32_t dA = g.sb + st * STG_BYTES;
        uint32_t dB = dA + TILE_A;
#pragma unroll
        for (int i = 0; i < 4; i++) {
            int row = ld_row + i * 32;
            CP_ASYNC16(dA + row * AP_BYTES + ld_c16 * 16, gA + (size_t)row * GK + ld_c16 * 8);
            CP_ASYNC16(dB + row * AP_BYTES + ld_c16 * 16, gB + (size_t)row * GK + ld_c16 * 8);
        }
    };

    load_tile(0, 0);
    CP_COMMIT();
    load_tile(1, 1);
    CP_COMMIT();

    int stg = 0;
    for (int kt = 0; kt < nch; kt++) {
        if (kt + 1 < nch) { CP_WAIT(1); } else { CP_WAIT(0); }
        __syncthreads();
        if (kt + 2 < nch) {
            int nstg = stg + 2; if (nstg >= 3) nstg -= 3;
            load_tile(nstg, kt + 2);
            CP_COMMIT();
        }
        const uint32_t sA = g.sb + stg * STG_BYTES;
        const uint32_t sB = sA + TILE_A;
#pragma unroll
        for (int ks = 0; ks < 4; ks++) {
            uint32_t a[4][4];
#pragma unroll
            for (int mi = 0; mi < 4; mi++) {
                uint32_t row = (uint32_t)(g.wm * 64 + mi * 16 + g.a_row_off);
                LDSM_X4(a[mi], sA + row * AP_BYTES + ks * 32 + g.a_kh * 16);
            }
            uint32_t b[4][2];
#pragma unroll
            for (int j2 = 0; j2 < 2; j2++) {
                uint32_t row = (uint32_t)(g.wn * 32 + j2 * 16 + g.b_n_off);
                uint32_t t[4];
                LDSM_X4(t, sB + row * AP_BYTES + ks * 32 + g.b_kh * 16);
                b[2 * j2][0] = t[0]; b[2 * j2][1] = t[1];
                b[2 * j2 + 1][0] = t[2]; b[2 * j2 + 1][1] = t[3];
            }
#pragma unroll
            for (int mi = 0; mi < 4; mi++)
#pragma unroll
                for (int nj = 0; nj < 4; nj++)
                    MMA16816(acc[mi][nj], a[mi], b[nj]);
        }
        if (++stg == 3) stg = 0;
    }
}

__device__ __forceinline__ GemmCtx make_ctx(uint32_t sb) {
    const int tid = threadIdx.x;
    GemmCtx g;
    g.sb = sb;
    const int wid = tid >> 5;
    g.lane = tid & 31;
    g.wm = wid >> 2; g.wn = wid & 3;
    const int lr = g.lane & 7, sel = g.lane >> 3;
    g.a_row_off = ((sel & 1) << 3) + lr;
    g.a_kh = sel >> 1;
    g.b_n_off = ((sel >> 1) << 3) + lr;
    g.b_kh = sel & 1;
    return g;
}

// ---------------------------------------------------------------------------
// gemm_qkv: fused Q/K/V projection. blockIdx.z: 0=Q->q6, 1=K->k6, 2=V->VT.
// ---------------------------------------------------------------------------
__global__ __launch_bounds__(256, 2)
void gemm_qkv(const __nv_bfloat16* __restrict__ A, const __nv_bfloat16* __restrict__ B2all,
              __nv_bfloat16* __restrict__ q6, __nv_bfloat16* __restrict__ k6,
              __nv_bfloat16* __restrict__ VT, float qscale)
{
    extern __shared__ __align__(128) char smemf[];
    GemmCtx g = make_ctx(smem_u32(smemf));
    const int z = blockIdx.z;
    const int bm = blockIdx.y * 128;
    const int bn = blockIdx.x * 128;
    const __nv_bfloat16* B = B2all + (size_t)z * DM * GK;
    const int nch = (z == 2) ? NCH3 : NCH6;

    float acc[4][4][4];
#pragma unroll
    for (int i = 0; i < 4; i++)
#pragma unroll
        for (int j = 0; j < 4; j++)
#pragma unroll
            for (int e = 0; e < 4; e++) acc[i][j][e] = 0.f;

    gemm_mainloop(A, B, bm, bn, nch, g, acc);

    // stage fp32 tile in smem (mainloop smem dead after final chunk)
    __syncthreads();
    float* stg = (float*)smemf;
    const int col = (g.lane & 3) * 2;
    const int rbase = g.lane >> 2;
#pragma unroll
    for (int mi = 0; mi < 4; mi++) {
#pragma unroll
        for (int nj = 0; nj < 4; nj++) {
            int row = g.wm * 64 + mi * 16 + rbase;
            int c0 = g.wn * 32 + nj * 8 + col;
            stg[row * EPI_P + c0]     = acc[mi][nj][0];
            stg[row * EPI_P + c0 + 1] = acc[mi][nj][1];
            stg[(row + 8) * EPI_P + c0]     = acc[mi][nj][2];
            stg[(row + 8) * EPI_P + c0 + 1] = acc[mi][nj][3];
        }
    }
    __syncthreads();

    const int wid = threadIdx.x >> 5;
    const int lane = g.lane;

    if (z == 2) {
        // V: write split transposed layout VT[bh][Vh d | Vl d][s] directly.
        const int b = bm >> 11;
        const int s0 = bm & 2047;
        for (int task = wid; task < 128; task += 8) {
            int h2 = task >> 6, d = task & 63;
            int bh = b * 16 + (bn >> 6) + h2;
            __nv_bfloat16* baseH = VT + ((size_t)bh * 128 + d) * SEQ + s0;
            __nv_bfloat16* baseL = baseH + (size_t)64 * SEQ;
#pragma unroll
            for (int j = 0; j < 4; j++) {
                int ss = lane + j * 32;
                float v = stg[ss * EPI_P + h2 * 64 + d];
                __nv_bfloat16 hh = __float2bfloat16(v);
                baseH[ss] = hh;
                baseL[ss] = __float2bfloat16(v - __bfloat162float(hh));
            }
        }
        return;
    }

    // Q/K: [h,m,l] split epilogue -> q6 / k6
    __nv_bfloat16* Y = (z == 0) ? q6 : k6;
    const float scale = (z == 0) ? qscale : 1.0f;
    for (int task = wid; task < 256; task += 8) {
        int tok = task >> 1;
        int h2 = task & 1;
        int row = bm + tok;
        int b = row >> 11, s = row & 2047;
        int head = (bn >> 6) + h2;
        float v0 = stg[tok * EPI_P + h2 * 64 + lane * 2]     * scale;
        float v1 = stg[tok * EPI_P + h2 * 64 + lane * 2 + 1] * scale;
        __nv_bfloat16* base = Y + ((size_t)(b * 16 + head) * SEQ + s) * 192 + lane * 2;
        store_split_hml(base, 64, v0, v1);
    }
}

// gemm_mma: plain fp32 output (fc_out)
__global__ __launch_bounds__(256, 2)
void gemm_mma(const __nv_bfloat16* __restrict__ A, const __nv_bfloat16* __restrict__ B,
              float* __restrict__ C, int nch)
{
    extern __shared__ __align__(128) char smem2[];
    GemmCtx g = make_ctx(smem_u32(smem2));
    const int bm = blockIdx.y * 128;
    const int bn = blockIdx.x * 128;

    float acc[4][4][4];
#pragma unroll
    for (int i = 0; i < 4; i++)
#pragma unroll
        for (int j = 0; j < 4; j++)
#pragma unroll
            for (int e = 0; e < 4; e++) acc[i][j][e] = 0.f;

    gemm_mainloop(A, B, bm, bn, nch, g, acc);

    const int col = (g.lane & 3) * 2;
    const int rbase = g.lane >> 2;
#pragma unroll
    for (int mi = 0; mi < 4; mi++) {
#pragma unroll
        for (int nj = 0; nj < 4; nj++) {
            int row = bm + g.wm * 64 + mi * 16 + rbase;
            int c0 = bn + g.wn * 32 + nj * 8 + col;
            *(float2*)&C[(size_t)row * DM + c0] =
                make_float2(acc[mi][nj][0], acc[mi][nj][1]);
            *(float2*)&C[(size_t)(row + 8) * DM + c0] =
                make_float2(acc[mi][nj][2], acc[mi][nj][3]);
        }
    }
}

// ---------------------------------------------------------------------------
// attn_tc: tensor-core flash attention, 128-key tiles (softmax amortized),
// 2-stage K/V pipeline; staged coalesced [h,m,h] epilogue into A2.
// ---------------------------------------------------------------------------
__global__ __launch_bounds__(256, 1)
void attn_tc(const __nv_bfloat16* __restrict__ Q6, const __nv_bfloat16* __restrict__ K6,
             const __nv_bfloat16* __restrict__ VT, __nv_bfloat16* __restrict__ A2)
{
    extern __shared__ __align__(128) char asm_[];
    const uint32_t sb = smem_u32(asm_);
    const uint32_t Qs = sb;
    const uint32_t Ks0 = sb + QS_BYTES;
    const uint32_t Vs0 = Ks0 + 2 * KS_BYTES;

    const int tid = threadIdx.x;
    const int w = tid >> 5, lane = tid & 31;
    const int bh = blockIdx.y;
    const int q0 = blockIdx.x * AQT;

    const int lr = lane & 7, sel = lane >> 3;
    const int a_row_off = ((sel & 1) << 3) + lr;
    const int a_kh = sel >> 1;
    const int b_n_off = ((sel >> 1) << 3) + lr;
    const int b_kh = sel & 1;

    const char* gQ = (const char*)(Q6 + ((size_t)bh * SEQ + q0) * 192);
    const char* gK = (const char*)(K6 + (size_t)bh * SEQ * 192);
    const char* gV = (const char*)(VT + (size_t)bh * 128 * SEQ);

    auto load_kv = [&](int st, int t) {
        const int k0 = t * AKT;
        uint32_t dK = Ks0 + st * KS_BYTES;
#pragma unroll
        for (int i = 0; i < 12; i++) {           // 128 rows * 24 chunks
            int idx = tid + i * 256;
            int row = idx / 24, c = idx % 24;
            CP_ASYNC16(dK + row * QKP + c * 16, gK + (size_t)(k0 + row) * 384 + c * 16);
        }
        uint32_t dV = Vs0 + st * VS_BYTES;
#pragma unroll
        for (int i = 0; i < 8; i++) {            // 128 rows * 16 chunks
            int idx = tid + i * 256;
            int row = idx >> 4, c = idx & 15;
            CP_ASYNC16(dV + row * VVP + c * 16, gV + ((size_t)row * SEQ + k0) * 2 + c * 16);
        }
    };

#pragma unroll
    for (int i = 0; i < 12; i++) {
        int idx = tid + i * 256;
        int row = idx / 24, c = idx % 24;
        CP_ASYNC16(Qs + row * QKP + c * 16, gQ + (size_t)row * 384 + c * 16);
    }
    load_kv(0, 0);
    CP_COMMIT();
    load_kv(1, 1);
    CP_COMMIT();

    uint32_t qa[3][4][4];
    float d[8][4];
#pragma unroll
    for (int i = 0; i < 8; i++)
#pragma unroll
        for (int e = 0; e < 4; e++) d[i][e] = 0.f;
    float m_lo = -1e30f, m_hi = -1e30f, l_lo = 0.f, l_hi = 0.f;

    const int NIT = SEQ / AKT;                   // 16
    for (int it = 0; it < NIT; it++) {
        if (it + 1 < NIT) { CP_WAIT(1); } else { CP_WAIT(0); }
        __syncthreads();

        if (it == 0) {
#pragma unroll
            for (int r = 0; r < 3; r++)
#pragma unroll
                for (int t4 = 0; t4 < 4; t4++)
                    LDSM_X4(qa[r][t4],
                            Qs + (w * 16 + a_row_off) * QKP + r * 128 + t4 * 32 + a_kh * 16);
        }

        const int st = it & 1;
        const uint32_t Ks = Ks0 + st * KS_BYTES;
        const uint32_t Vs = Vs0 + st * VS_BYTES;

        // ---- S = Q K^T over 128 keys (8 kb blocks) ----
        float c[16][4];
#pragma unroll
        for (int i = 0; i < 16; i++)
#pragma unroll
            for (int e = 0; e < 4; e++) c[i][e] = 0.f;

#pragma unroll
        for (int kb = 0; kb < 8; kb++) {
            const uint32_t krow = Ks + (kb * 16 + b_n_off) * QKP + b_kh * 16;
#pragma unroll
            for (int t4 = 0; t4 < 4; t4++) {
                uint32_t bb[4];
                LDSM_X4(bb, krow + 0 * 128 + t4 * 32);
                MMA16816(c[kb * 2],     qa[0][t4], bb);
                MMA16816(c[kb * 2 + 1], qa[0][t4], bb + 2);
                MMA16816(c[kb * 2],     qa[1][t4], bb);
                MMA16816(c[kb * 2 + 1], qa[1][t4], bb + 2);
                MMA16816(c[kb * 2],     qa[2][t4], bb);
                MMA16816(c[kb * 2 + 1], qa[2][t4], bb + 2);
                LDSM_X4(bb, krow + 1 * 128 + t4 * 32);
                MMA16816(c[kb * 2],     qa[0][t4], bb);
                MMA16816(c[kb * 2 + 1], qa[0][t4], bb + 2);
                MMA16816(c[kb * 2],     qa[1][t4], bb);
                MMA16816(c[kb * 2 + 1], qa[1][t4], bb + 2);
                LDSM_X4(bb, krow + 2 * 128 + t4 * 32);
                MMA16816(c[kb * 2],     qa[0][t4], bb);
                MMA16816(c[kb * 2 + 1], qa[0][t4], bb + 2);
            }
        }

        // ---- online softmax over 128 keys (log2 domain) ----
        float tmx_lo = -1e30f, tmx_hi = -1e30f;
#pragma unroll
        for (int t = 0; t < 16; t++) {
            tmx_lo = fmaxf(tmx_lo, fmaxf(c[t][0], c[t][1]));
            tmx_hi = fmaxf(tmx_hi, fmaxf(c[t][2], c[t][3]));
        }
        tmx_lo = fmaxf(tmx_lo, __shfl_xor_sync(0xffffffffu, tmx_lo, 1));
        tmx_lo = fmaxf(tmx_lo, __shfl_xor_sync(0xffffffffu, tmx_lo, 2));
        tmx_hi = fmaxf(tmx_hi, __shfl_xor_sync(0xffffffffu, tmx_hi, 1));
        tmx_hi = fmaxf(tmx_hi, __shfl_xor_sync(0xffffffffu, tmx_hi, 2));

        float mn_lo = fmaxf(m_lo, tmx_lo);
        float mn_hi = fmaxf(m_hi, tmx_hi);
        float corr_lo = exp2f(m_lo - mn_lo);
        float corr_hi = exp2f(m_hi - mn_hi);

        float ps_lo = 0.f, ps_hi = 0.f;
#pragma unroll
        for (int t = 0; t < 16; t++) {
            c[t][0] = exp2f(c[t][0] - mn_lo);
            c[t][1] = exp2f(c[t][1] - mn_lo);
            c[t][2] = exp2f(c[t][2] - mn_hi);
            c[t][3] = exp2f(c[t][3] - mn_hi);
            ps_lo += c[t][0] + c[t][1];
            ps_hi += c[t][2] + c[t][3];
        }
        ps_lo += __shfl_xor_sync(0xffffffffu, ps_lo, 1);
        ps_lo += __shfl_xor_sync(0xffffffffu, ps_lo, 2);
        ps_hi += __shfl_xor_sync(0xffffffffu, ps_hi, 1);
        ps_hi += __shfl_xor_sync(0xffffffffu, ps_hi, 2);
        l_lo = l_lo * corr_lo + ps_lo;
        l_hi = l_hi * corr_hi + ps_hi;
        m_lo = mn_lo; m_hi = mn_hi;
#pragma unroll
        for (int nb = 0; nb < 8; nb++) {
            d[nb][0] *= corr_lo; d[nb][1] *= corr_lo;
            d[nb][2] *= corr_hi; d[nb][3] *= corr_hi;
        }

        // ---- PV in two 64-key halves (reuse aph/apl registers) ----
#pragma unroll
        for (int half = 0; half < 2; half++) {
            uint32_t aph[4][4], apl[4][4];
#pragma unroll
            for (int kt = 0; kt < 4; kt++) {
                int t0 = half * 8 + 2 * kt, t1 = t0 + 1;
                aph[kt][0] = pack_bf16x2(c[t0][0], c[t0][1]);
                aph[kt][1] = pack_bf16x2(c[t0][2], c[t0][3]);
                aph[kt][2] = pack_bf16x2(c[t1][0], c[t1][1]);
                aph[kt][3] = pack_bf16x2(c[t1][2], c[t1][3]);
                apl[kt][0] = residual_bf16x2(c[t0][0], c[t0][1], aph[kt][0]);
                apl[kt][1] = residual_bf16x2(c[t0][2], c[t0][3], aph[kt][1]);
                apl[kt][2] = residual_bf16x2(c[t1][0], c[t1][1], aph[kt][2]);
                apl[kt][3] = residual_bf16x2(c[t1][2], c[t1][3], aph[kt][3]);
            }
#pragma unroll
            for (int nbp = 0; nbp < 4; nbp++) {
                const uint32_t vrow = Vs + (nbp * 16 + b_n_off) * VVP + half * 128 + b_kh * 16;
#pragma unroll
                for (int kt = 0; kt < 4; kt++) {
                    uint32_t tH[4], tL[4];
                    LDSM_X4(tH, vrow + kt * 32);
                    LDSM_X4(tL, vrow + 64 * VVP + kt * 32);
                    MMA16816(d[nbp * 2],     aph[kt], tH);
                    MMA16816(d[nbp * 2 + 1], aph[kt], tH + 2);
                    MMA16816(d[nbp * 2],     apl[kt], tH);
                    MMA16816(d[nbp * 2 + 1], apl[kt], tH + 2);
                    MMA16816(d[nbp * 2],     aph[kt], tL);
                    MMA16816(d[nbp * 2 + 1], aph[kt], tL + 2);
                }
            }
        }

        __syncthreads();
        if (it + 2 < NIT) {
            load_kv(it & 1, it + 2);
            CP_COMMIT();
        }
    }

    // ---- staged coalesced epilogue: [h,m,h] A-split into A2 regions 0..2 ----
    float inv_lo = 1.f / l_lo, inv_hi = 1.f / l_hi;
    float* stg = (float*)asm_;
    const int row0 = w * 16 + (lane >> 2);
    const int colb = (lane & 3) * 2;
#pragma unroll
    for (int nb = 0; nb < 8; nb++) {
        stg[row0 * AEPI_P + colb + nb * 8]     = d[nb][0] * inv_lo;
        stg[row0 * AEPI_P + colb + nb * 8 + 1] = d[nb][1] * inv_lo;
        stg[(row0 + 8) * AEPI_P + colb + nb * 8]     = d[nb][2] * inv_hi;
        stg[(row0 + 8) * AEPI_P + colb + nb * 8 + 1] = d[nb][3] * inv_hi;
    }
    __syncthreads();

    const int h = bh & 15;
    const int btok = (bh >> 4) * SEQ;
    for (int task = w; task < 128; task += 8) {
        int row = btok + q0 + task;
        float v0 = stg[task * AEPI_P + lane * 2];
        float v1 = stg[task * AEPI_P + lane * 2 + 1];
        __nv_bfloat16* base = A2 + (size_t)row * GK + h * 64 + lane * 2;
        store_split_hmh(base, 1024, v0, v1);
    }
}

// ---------------------------------------------------------------------------
extern "C" void kernel_launch(void* const* d_in, const int* in_sizes, int n_in,
                              void* d_out, int out_size)
{
    const float* x  = (const float*)d_in[0];
    const float* Wq = (const float*)d_in[1];
    const float* Wk = (const float*)d_in[2];
    const float* Wv = (const float*)d_in[3];
    const float* Wo = (const float*)d_in[4];
    float* out = (float*)d_out;

    __nv_bfloat16 *a2, *b2, *q6, *k6, *vt;
    cudaGetSymbolAddress((void**)&a2, g_A2);
    cudaGetSymbolAddress((void**)&b2, g_B2);
    cudaGetSymbolAddress((void**)&q6, g_Q6);
    cudaGetSymbolAddress((void**)&k6, g_K6);
    cudaGetSymbolAddress((void**)&vt, g_VT);
    __nv_bfloat16* b2o = b2 + 3 * (size_t)DM * GK;

    cudaFuncSetAttribute(gemm_qkv, cudaFuncAttributeMaxDynamicSharedMemorySize, GEMM_SMEM);
    cudaFuncSetAttribute(gemm_mma, cudaFuncAttributeMaxDynamicSharedMemorySize, GEMM_SMEM);
    cudaFuncSetAttribute(attn_tc, cudaFuncAttributeMaxDynamicSharedMemorySize, ATTN_SMEM);

    const int convA_blocks = (int)(((size_t)TOK * DM) / 256);
    const float qscale = 0.125f * 1.4426950408889634f;

    convert_A<<<convA_blocks, 256>>>(x, a2);                               // 1
    dim3 convB_grid(16, 8, 4);
    convert_B4<<<convB_grid, 256>>>(Wq, Wk, Wv, Wo, b2);                   // 2

    dim3 qkv_grid(DM / 128, TOK / 128, 3);                                 // 1536 CTAs
    gemm_qkv<<<qkv_grid, 256, GEMM_SMEM>>>(a2, b2, q6, k6, vt, qscale);    // 3

    dim3 agrid(SEQ / AQT, 64);                                             // (16, 64)
    attn_tc<<<agrid, 256, ATTN_SMEM>>>(q6, k6, vt, a2);                    // 4 -> A2 [h,m,h]

    dim3 ggrid(DM / 128, TOK / 128);
    gemm_mma<<<ggrid, 256, GEMM_SMEM>>>(a2, b2o, out, NCH3);               // 5 fc_out
}